// round 16
// baseline (speedup 1.0000x reference)
#include <cuda_runtime.h>
#include <cuda_fp16.h>

#define TT   2048
#define BB   4
#define HH   16
#define HD   64
#define EE   1024
#define NBH  64
#define ROWS 64
#define SCH  256
#define NCH  (TT / SCH)

#define OST  68      // sO fp32 word stride

// smem byte offsets (attn)
#define OFFB_K0  0            // [256][144B] = 36864
#define OFFB_K1  36864
#define OFFB_V0  73728
#define OFFB_V1  110592
#define OFFB_W   147456       // [64 rows][528 B] = 33792 (reused as sO fp32 [64][68])
#define OFFB_Q   181248       // [64 rows][144 B] = 9216
#define OFFB_ML  190464       // l: 64*8 fp32 = 2048
#define SMEM_BYTES 194560

// proj smem
#define PSM_X    0
#define PSM_W    18432
#define PSM_B    46080
#define PSM_BYTES 46848

// plain fp16 planes, [bh][t][d]
__device__ __half g_q[(size_t)NBH * TT * HD];
__device__ __half g_k[(size_t)NBH * TT * HD];
__device__ __half g_v[(size_t)NBH * TT * HD];
// unnormalized p-hat, one plane per head: [bh][t][s]
__device__ __half g_p[(size_t)NBH * TT * TT];
__device__ float  g_il[(size_t)NBH * TT];

// ---------------------------------------------------------------------------
__device__ __forceinline__ void mma_f16(float* d, const unsigned* a,
                                        unsigned b0, unsigned b1) {
    asm volatile("mma.sync.aligned.m16n8k16.row.col.f32.f16.f16.f32 "
                 "{%0,%1,%2,%3}, {%4,%5,%6,%7}, {%8,%9}, {%0,%1,%2,%3};"
                 : "+f"(d[0]), "+f"(d[1]), "+f"(d[2]), "+f"(d[3])
                 : "r"(a[0]), "r"(a[1]), "r"(a[2]), "r"(a[3]), "r"(b0), "r"(b1));
}
__device__ __forceinline__ void ldmx4(unsigned* r, unsigned saddr) {
    asm volatile("ldmatrix.sync.aligned.m8n8.x4.shared.b16 {%0,%1,%2,%3}, [%4];"
                 : "=r"(r[0]), "=r"(r[1]), "=r"(r[2]), "=r"(r[3]) : "r"(saddr));
}
__device__ __forceinline__ void ldmx4t(unsigned* r, unsigned saddr) {
    asm volatile("ldmatrix.sync.aligned.m8n8.x4.trans.shared.b16 {%0,%1,%2,%3}, [%4];"
                 : "=r"(r[0]), "=r"(r[1]), "=r"(r[2]), "=r"(r[3]) : "r"(saddr));
}
__device__ __forceinline__ unsigned pack2h(float a, float b) {
    __half2 h = __floats2half2_rn(a, b);
    return *(unsigned*)&h;
}
__device__ __forceinline__ void cpa16(unsigned saddr, const void* gaddr) {
    asm volatile("cp.async.cg.shared.global [%0], [%1], 16;" :: "r"(saddr), "l"(gaddr));
}
#define CP_COMMIT() asm volatile("cp.async.commit_group;")
#define CP_WAIT0()  asm volatile("cp.async.wait_group 0;")

// PV reduction helpers (pv layout: [mi][dnt][u2*4 + frag]; slot = 32x64 fp32)
__device__ __forceinline__ void red_store(float* red, int slot, const float pv[2][4][8],
                                          int g, int q)
{
    #pragma unroll
    for (int mi = 0; mi < 2; mi++)
        #pragma unroll
        for (int dnt = 0; dnt < 4; dnt++)
            #pragma unroll
            for (int u2 = 0; u2 < 2; u2++) {
                *(float2*)&red[slot * 2048 + (mi * 16 + g) * 64 + dnt * 16 + u2 * 8 + 2 * q] =
                    make_float2(pv[mi][dnt][u2 * 4 + 0], pv[mi][dnt][u2 * 4 + 1]);
                *(float2*)&red[slot * 2048 + (mi * 16 + g + 8) * 64 + dnt * 16 + u2 * 8 + 2 * q] =
                    make_float2(pv[mi][dnt][u2 * 4 + 2], pv[mi][dnt][u2 * 4 + 3]);
            }
}
__device__ __forceinline__ void red_load(const float* red, int slot, float pv[2][4][8],
                                         int g, int q)
{
    #pragma unroll
    for (int mi = 0; mi < 2; mi++)
        #pragma unroll
        for (int dnt = 0; dnt < 4; dnt++)
            #pragma unroll
            for (int u2 = 0; u2 < 2; u2++) {
                float2 p0 = *(const float2*)&red[slot * 2048 + (mi * 16 + g) * 64 + dnt * 16 + u2 * 8 + 2 * q];
                float2 p1 = *(const float2*)&red[slot * 2048 + (mi * 16 + g + 8) * 64 + dnt * 16 + u2 * 8 + 2 * q];
                pv[mi][dnt][u2 * 4 + 0] += p0.x; pv[mi][dnt][u2 * 4 + 1] += p0.y;
                pv[mi][dnt][u2 * 4 + 2] += p1.x; pv[mi][dnt][u2 * 4 + 3] += p1.y;
            }
}

// ---------------------------------------------------------------------------
// Kernel 1: QKV projection as fp16 tensor-core GEMM (verified R15).
// ---------------------------------------------------------------------------
extern "C" __global__ void __launch_bounds__(512)
proj_kernel(const float* __restrict__ x,
            const float* __restrict__ w,
            const float* __restrict__ bias)
{
    extern __shared__ char psm[];
    float* sB = (float*)(psm + PSM_B);

    const int ct0 = blockIdx.x * 128;
    const int tid  = threadIdx.x;
    const int lane = tid & 31;
    const int wid  = tid >> 5;
    const int mw2  = wid & 3;
    const int nww  = wid >> 2;
    const int g    = lane >> 2;
    const int q    = lane & 3;

    #pragma unroll 2
    for (int i = tid; i < 192 * 32; i += 512) {
        const int j = i >> 5, dw = i & 31;
        const float2 v = *(const float2*)&w[j * 64 + dw * 2];
        *(unsigned*)(psm + PSM_W + j * 144 + dw * 4) = pack2h(v.x, v.y);
    }
    #pragma unroll 2
    for (int i = tid; i < 128 * 32; i += 512) {
        const int r = i >> 5, dw = i & 31;
        const float2 v = *(const float2*)&x[(size_t)(ct0 + r) * 64 + dw * 2];
        *(unsigned*)(psm + PSM_X + r * 144 + dw * 4) = pack2h(v.x, v.y);
    }
    if (tid < 192) sB[tid] = bias[tid];
    __syncthreads();

    const unsigned sX_sa = (unsigned)__cvta_generic_to_shared(psm + PSM_X);
    const unsigned sW_sa = (unsigned)__cvta_generic_to_shared(psm + PSM_W);
    const unsigned ax_b0 = sX_sa + (unsigned)((mw2 * 32 + (lane & 15)) * 144 + ((lane >> 4) & 1) * 16);
    const unsigned ax_b1 = ax_b0 + 16 * 144;
    const unsigned bw_row = (unsigned)(nww * 48 + ((lane >> 4) & 1) * 8 + (lane & 7));
    const unsigned bw_kc  = (unsigned)(((lane >> 3) & 1) * 16);

    float acc[2][6][4];
    #pragma unroll
    for (int mi = 0; mi < 2; mi++)
        #pragma unroll
        for (int n8 = 0; n8 < 6; n8++)
            #pragma unroll
            for (int u = 0; u < 4; u++) acc[mi][n8][u] = 0.f;

    #pragma unroll
    for (int jb = 0; jb < 4; jb++) {
        unsigned a0[4], a1[4];
        ldmx4(a0, ax_b0 + jb * 32);
        ldmx4(a1, ax_b1 + jb * 32);
        #pragma unroll
        for (int nt = 0; nt < 3; nt++) {
            unsigned bk[4];
            ldmx4(bk, sW_sa + (bw_row + nt * 16) * 144 + jb * 32 + bw_kc);
            mma_f16(acc[0][2 * nt],     a0, bk[0], bk[1]);
            mma_f16(acc[0][2 * nt + 1], a0, bk[2], bk[3]);
            mma_f16(acc[1][2 * nt],     a1, bk[0], bk[1]);
            mma_f16(acc[1][2 * nt + 1], a1, bk[2], bk[3]);
        }
    }

    #pragma unroll
    for (int mi = 0; mi < 2; mi++) {
        #pragma unroll
        for (int hf = 0; hf < 2; hf++) {
            const int rg = ct0 + mw2 * 32 + mi * 16 + hf * 8 + g;
            const int h  = rg & 15;
            const int b  = (rg >> 4) & 3;
            const int t  = rg >> 6;
            const size_t rowbase = ((size_t)(b * 16 + h) * TT + t) * HD;
            #pragma unroll
            for (int n8 = 0; n8 < 6; n8++) {
                const int j0 = nww * 48 + n8 * 8 + 2 * q;
                float v0 = acc[mi][n8][hf * 2]     + sB[j0];
                float v1 = acc[mi][n8][hf * 2 + 1] + sB[j0 + 1];
                if (j0 < 64) {
                    *(unsigned*)&g_q[rowbase + j0] = pack2h(v0 * 0.125f, v1 * 0.125f);
                } else if (j0 < 128) {
                    *(unsigned*)&g_k[rowbase + (j0 - 64)] = pack2h(v0, v1);
                } else {
                    *(unsigned*)&g_v[rowbase + (j0 - 128)] = pack2h(v0, v1);
                }
            }
        }
    }
}

// ---------------------------------------------------------------------------
__device__ __forceinline__ void stage_k(unsigned sbase, const __half* gsrc,
                                        size_t rowbase, int tid)
{
    #pragma unroll
    for (int i = tid; i < SCH * 8; i += 512) {
        const int s = i >> 3, j = i & 7;
        cpa16(sbase + s * 144 + j * 16, (const void*)(((const uint4*)gsrc) + (rowbase + s) * 8 + j));
    }
}

// ---------------------------------------------------------------------------
// Kernel 2: single-pass flash attention (m=0), own-data PV.
// Warp (mw 0..1: 32-row m-tile, sw 0..7: 32-s slice). PV: k = own 32 s, n = 64 d.
// One __syncthreads per chunk (staging flip, race-free: stage AFTER barrier).
// ---------------------------------------------------------------------------
extern "C" __global__ void __launch_bounds__(512, 1)
attn_kernel(const float* __restrict__ outw,
            const float* __restrict__ outb,
            float* __restrict__ out)    // [T][B][E]
{
    extern __shared__ char smc[];
    float* SML = (float*)(smc + OFFB_ML);           // [64][8] l partials

    const int b    = blockIdx.x;
    const int t0   = blockIdx.y * ROWS;
    const int tid  = threadIdx.x;
    const int lane = tid & 31;
    const int wid  = tid >> 5;
    const int mw   = wid >> 3;          // 0..1
    const int sw   = wid & 7;           // 0..7
    const int g    = lane >> 2;
    const int q    = lane & 3;

    const unsigned smem_sa = (unsigned)__cvta_generic_to_shared(smc);
    const unsigned sK0 = smem_sa + OFFB_K0;
    const unsigned sK1 = smem_sa + OFFB_K1;
    const unsigned sV0 = smem_sa + OFFB_V0;
    const unsigned sV1 = smem_sa + OFFB_V1;
    const unsigned sW_sa = smem_sa + OFFB_W;
    const unsigned sQ_sa = smem_sa + OFFB_Q;

    // fragment address components
    const unsigned aq_b0 = sQ_sa + (unsigned)((mw * 32 + (lane & 15)) * 144 + ((lane >> 4) & 1) * 16);
    const unsigned aq_b1 = aq_b0 + 16 * 144;
    const unsigned bk_row = (unsigned)(sw * 32 + ((lane >> 4) & 1) * 8 + (lane & 7));
    const unsigned bk_kc  = (unsigned)(((lane >> 3) & 1) * 16);
    const unsigned bv_row = (unsigned)(sw * 32 + ((lane >> 3) & 1) * 8 + (lane & 7));
    const unsigned bv_nc  = (unsigned)(((lane >> 4) & 1) * 16);
    // own-warp PV A-frags from W stage: rows mw*32 + mi*16 + (lane&15), cols sw*64B + kb*32B
    const unsigned aw_b0 = sW_sa + (unsigned)((mw * 32 + (lane & 15)) * 528 + sw * 64 + ((lane >> 4) & 1) * 16);
    const unsigned aw_b1 = aw_b0 + 16 * 528;

    for (int h = 0; h < HH; h++) {
        const int bh = b * HH + h;
        const size_t base = (size_t)bh * TT;

        // ---- prologue: stage Q + chunk 0 (issued after trailing head sync) ----
        {
            const int r = tid >> 3, j = tid & 7;
            cpa16(sQ_sa + (unsigned)(r * 144 + j * 16),
                  (const void*)(((const uint4*)g_q) + (base + t0 + r) * 8 + j));
        }
        stage_k(sK0, g_k, base, tid);
        stage_k(sV0, g_v, base, tid);
        CP_COMMIT();

        float pv[2][4][8];
        #pragma unroll
        for (int mi = 0; mi < 2; mi++)
            #pragma unroll
            for (int dnt = 0; dnt < 4; dnt++)
                #pragma unroll
                for (int u = 0; u < 8; u++) pv[mi][dnt][u] = 0.f;
        float lp[2][2] = {{0.f, 0.f}, {0.f, 0.f}};

        for (int c = 0; c < NCH; c++) {
            CP_WAIT0();
            __syncthreads();                         // all reads of prev buffer done
            if (c + 1 < NCH) {                       // stage next AFTER barrier (race-free)
                stage_k((c & 1) ? sK0 : sK1, g_k, base + (size_t)(c + 1) * SCH, tid);
                stage_k((c & 1) ? sV0 : sV1, g_v, base + (size_t)(c + 1) * SCH, tid);
                CP_COMMIT();
            }
            const unsigned sK_sa = (c & 1) ? sK1 : sK0;
            const unsigned sV_sa = (c & 1) ? sV1 : sV0;
            const int s0g = c * SCH;

            // aq reload per chunk (frees registers for the wide PV accumulator)
            unsigned aq[2][4][4];
            #pragma unroll
            for (int jb = 0; jb < 4; jb++) {
                ldmx4(aq[0][jb], aq_b0 + jb * 32);
                ldmx4(aq[1][jb], aq_b1 + jb * 32);
            }

            // scores (2 n16 tiles) -> exp -> l -> pack to own W region
            #pragma unroll
            for (int nt = 0; nt < 2; nt++) {
                float sc2[2][8];
                #pragma unroll
                for (int mi = 0; mi < 2; mi++)
                    #pragma unroll
                    for (int u = 0; u < 8; u++) sc2[mi][u] = 0.f;
                #pragma unroll
                for (int jb = 0; jb < 4; jb++) {
                    unsigned bk[4];
                    ldmx4(bk, sK_sa + (bk_row + nt * 16) * 144 + jb * 32 + bk_kc);
                    #pragma unroll
                    for (int mi = 0; mi < 2; mi++) {
                        mma_f16(sc2[mi],     aq[mi][jb], bk[0], bk[1]);
                        mma_f16(sc2[mi] + 4, aq[mi][jb], bk[2], bk[3]);
                    }
                }
                #pragma unroll
                for (int mi = 0; mi < 2; mi++) {
                    #pragma unroll
                    for (int u2 = 0; u2 < 2; u2++) {
                        const float p00 = __expf(sc2[mi][u2 * 4 + 0]);
                        const float p01 = __expf(sc2[mi][u2 * 4 + 1]);
                        const float p10 = __expf(sc2[mi][u2 * 4 + 2]);
                        const float p11 = __expf(sc2[mi][u2 * 4 + 3]);
                        lp[mi][0] += p00 + p01;
                        lp[mi][1] += p10 + p11;
                        const int cloc = sw * 32 + nt * 16 + u2 * 8 + 2 * q;
                        const int r0 = mw * 32 + mi * 16 + g;
                        *(unsigned*)(smc + OFFB_W + r0 * 528 + cloc * 2)       = pack2h(p00, p01);
                        *(unsigned*)(smc + OFFB_W + (r0 + 8) * 528 + cloc * 2) = pack2h(p10, p11);
                    }
                }
            }
            __syncwarp();                            // own-warp W region complete

            // own-region p-hat copy -> global (16B/lane, coalesced 64B segments)
            {
                __half* ps = g_p + ((size_t)bh * TT + t0) * TT + s0g;
                #pragma unroll
                for (int it = 0; it < 4; it++) {
                    const int r = mw * 32 + it * 8 + (lane >> 2);
                    const uint4 v = *(const uint4*)(smc + OFFB_W + r * 528 + sw * 64 + (lane & 3) * 16);
                    *(uint4*)(ps + (size_t)r * TT + sw * 32 + (lane & 3) * 8) = v;
                }
            }

            // PV: own 32 s as k (2 k16 blocks), n = all 64 d
            #pragma unroll
            for (int kb = 0; kb < 2; kb++) {
                unsigned aw0[4], aw1[4];
                ldmx4(aw0, aw_b0 + kb * 32);
                ldmx4(aw1, aw_b1 + kb * 32);
                #pragma unroll
                for (int dnt = 0; dnt < 4; dnt++) {
                    unsigned bv[4];
                    ldmx4t(bv, sV_sa + (bv_row + kb * 16) * 144 + dnt * 32 + bv_nc);
                    mma_f16(pv[0][dnt],     aw0, bv[0], bv[1]);
                    mma_f16(pv[0][dnt] + 4, aw0, bv[2], bv[3]);
                    mma_f16(pv[1][dnt],     aw1, bv[0], bv[1]);
                    mma_f16(pv[1][dnt] + 4, aw1, bv[2], bv[3]);
                }
            }
        }

        // ---- l reduction across q-lanes then 8 s-warps ----
        #pragma unroll
        for (int mi = 0; mi < 2; mi++)
            #pragma unroll
            for (int hf = 0; hf < 2; hf++) {
                float v = lp[mi][hf];
                v += __shfl_xor_sync(0xffffffffu, v, 1);
                v += __shfl_xor_sync(0xffffffffu, v, 2);
                lp[mi][hf] = v;
            }
        __syncthreads();                             // all PV reads of buffers done
        if (q == 0) {
            #pragma unroll
            for (int mi = 0; mi < 2; mi++)
                #pragma unroll
                for (int hf = 0; hf < 2; hf++) {
                    const int ri = mw * 32 + mi * 16 + hf * 8 + g;
                    SML[ri * 8 + sw] = lp[mi][hf];
                }
        }
        __syncthreads();
        float inv[2][2];
        #pragma unroll
        for (int mi = 0; mi < 2; mi++)
            #pragma unroll
            for (int hf = 0; hf < 2; hf++) {
                const int ri = mw * 32 + mi * 16 + hf * 8 + g;
                float lf = 0.f;
                #pragma unroll
                for (int i = 0; i < 8; i++) lf += SML[ri * 8 + i];
                inv[mi][hf] = 1.f / lf;
            }
        if (sw == 0 && q == 0) {
            #pragma unroll
            for (int mi = 0; mi < 2; mi++)
                #pragma unroll
                for (int hf = 0; hf < 2; hf++) {
                    const int ri = mw * 32 + mi * 16 + hf * 8 + g;
                    g_il[(size_t)bh * TT + t0 + ri] = inv[mi][hf] * (1.f / HH);
                }
        }

        // ---- PV 8-way reduction over sw (slots in staged-buffer region) ----
        float* red = (float*)(smc + OFFB_K0);        // 8 slots x 32x64 fp32 = 64KB
        if (sw >= 4) red_store(red, mw * 4 + (sw - 4), pv, g, q);
        __syncthreads();
        if (sw < 4) red_load(red, mw * 4 + sw, pv, g, q);
        __syncthreads();
        if (sw == 2 || sw == 3) red_store(red, mw * 4 + (sw - 2), pv, g, q);
        __syncthreads();
        if (sw < 2) red_load(red, mw * 4 + sw, pv, g, q);
        __syncthreads();
        if (sw == 1) red_store(red, mw * 4, pv, g, q);
        __syncthreads();
        float* so = (float*)(smc + OFFB_W);          // [64][OST] fp32
        if (sw == 0) {
            red_load(red, mw * 4, pv, g, q);
            #pragma unroll
            for (int mi = 0; mi < 2; mi++)
                #pragma unroll
                for (int dnt = 0; dnt < 4; dnt++)
                    #pragma unroll
                    for (int u2 = 0; u2 < 2; u2++) {
                        const int col = dnt * 16 + u2 * 8 + 2 * q;
                        const int r0  = mw * 32 + mi * 16 + g;
                        *(float2*)&so[r0 * OST + col] =
                            make_float2(pv[mi][dnt][u2 * 4 + 0] * inv[mi][0],
                                        pv[mi][dnt][u2 * 4 + 1] * inv[mi][0]);
                        *(float2*)&so[(r0 + 8) * OST + col] =
                            make_float2(pv[mi][dnt][u2 * 4 + 2] * inv[mi][1],
                                        pv[mi][dnt][u2 * 4 + 3] * inv[mi][1]);
                    }
        }
        __syncthreads();

        // ---- out projection ----
        {
            const int e  = tid & 63;
            const int rg = tid >> 6;
            float oc[8];
            const float ob = outb[e];
            #pragma unroll
            for (int k = 0; k < 8; k++) oc[k] = ob;
            #pragma unroll 8
            for (int d = 0; d < 64; d++) {
                const float wv = outw[e * HD + d];
                #pragma unroll
                for (int k = 0; k < 8; k++)
                    oc[k] += so[(rg * 8 + k) * OST + d] * wv;
            }
            #pragma unroll
            for (int k = 0; k < 8; k++)
                out[((size_t)(t0 + rg * 8 + k) * BB + b) * EE + h * HD + e] = oc[k];
        }
        __syncthreads();
    }
}

// ---------------------------------------------------------------------------
// Kernel 3: avg finalize (verified R14/R15).
// ---------------------------------------------------------------------------
extern "C" __global__ void __launch_bounds__(256)
avg_kernel(float* __restrict__ avg)     // [B][T][T]
{
    const int bt = blockIdx.x;
    const int b  = bt >> 11;
    const int t  = bt & (TT - 1);
    const int tid = threadIdx.x;

    __shared__ float il[HH];
    if (tid < HH) il[tid] = g_il[(size_t)(b * HH + tid) * TT + t];
    __syncthreads();

    const int s0 = tid * 8;
    float acc[8] = {};
    #pragma unroll
    for (int h = 0; h < HH; h++) {
        const uint4 pk = *(const uint4*)(g_p + ((size_t)(b * HH + h) * TT + t) * TT + s0);
        const float s = il[h];
        const __half2* ph = (const __half2*)&pk;
        #pragma unroll
        for (int j = 0; j < 4; j++) {
            float2 f = __half22float2(ph[j]);
            acc[2 * j]     += f.x * s;
            acc[2 * j + 1] += f.y * s;
        }
    }
    float* dst = avg + ((size_t)b * TT + t) * TT + s0;
    *(float4*)dst       = make_float4(acc[0], acc[1], acc[2], acc[3]);
    *(float4*)(dst + 4) = make_float4(acc[4], acc[5], acc[6], acc[7]);
}

// ---------------------------------------------------------------------------
extern "C" void kernel_launch(void* const* d_in, const int* in_sizes, int n_in,
                              void* d_out, int out_size)
{
    const float* x    = (const float*)d_in[0];
    const float* w    = (const float*)d_in[1];
    const float* bias = (const float*)d_in[2];
    const float* outw = (const float*)d_in[3];
    const float* outb = (const float*)d_in[4];

    float* out = (float*)d_out;
    float* avg = out + (size_t)TT * BB * EE;

    static bool attrs_set = false;
    if (!attrs_set) {
        cudaFuncSetAttribute(proj_kernel, cudaFuncAttributeMaxDynamicSharedMemorySize, PSM_BYTES);
        cudaFuncSetAttribute(attn_kernel, cudaFuncAttributeMaxDynamicSharedMemorySize, SMEM_BYTES);
        attrs_set = true;
    }

    proj_kernel<<<(TT * BB * HH) / 128, 512, PSM_BYTES>>>(x, w, bias);
    attn_kernel<<<dim3(BB, TT / ROWS), 512, SMEM_BYTES>>>(outw, outb, out);
    avg_kernel<<<BB * TT, 256>>>(avg);
}

// round 17
// speedup vs baseline: 1.0317x; 1.0317x over previous
#include <cuda_runtime.h>
#include <cuda_fp16.h>

#define TT   2048
#define BB   4
#define HH   16
#define HD   64
#define EE   1024
#define NBH  64
#define ROWS 64
#define SCH  256
#define NCH  (TT / SCH)

#define OST  68      // sO fp32 word stride

// smem byte offsets (attn)
#define OFFB_K0  0            // [256][144B] = 36864
#define OFFB_K1  36864
#define OFFB_V0  73728
#define OFFB_V1  110592
#define OFFB_W   147456       // [64 rows][528 B] = 33792 (reused as sO fp32 [64][68])
#define OFFB_Q   181248       // [64 rows][144 B] = 9216
#define OFFB_ML  190464       // l: 64*8 fp32 = 2048
#define SMEM_BYTES 194560

// proj smem
#define PSM_X    0
#define PSM_W    18432
#define PSM_B    46080
#define PSM_BYTES 46848

// plain fp16 planes, [bh][t][d]
__device__ __half g_q[(size_t)NBH * TT * HD];
__device__ __half g_k[(size_t)NBH * TT * HD];
__device__ __half g_v[(size_t)NBH * TT * HD];
// unnormalized p-hat, one plane per head: [bh][t][s]
__device__ __half g_p[(size_t)NBH * TT * TT];
__device__ float  g_il[(size_t)NBH * TT];

// ---------------------------------------------------------------------------
__device__ __forceinline__ void mma_f16(float* d, const unsigned* a,
                                        unsigned b0, unsigned b1) {
    asm volatile("mma.sync.aligned.m16n8k16.row.col.f32.f16.f16.f32 "
                 "{%0,%1,%2,%3}, {%4,%5,%6,%7}, {%8,%9}, {%0,%1,%2,%3};"
                 : "+f"(d[0]), "+f"(d[1]), "+f"(d[2]), "+f"(d[3])
                 : "r"(a[0]), "r"(a[1]), "r"(a[2]), "r"(a[3]), "r"(b0), "r"(b1));
}
__device__ __forceinline__ void ldmx4(unsigned* r, unsigned saddr) {
    asm volatile("ldmatrix.sync.aligned.m8n8.x4.shared.b16 {%0,%1,%2,%3}, [%4];"
                 : "=r"(r[0]), "=r"(r[1]), "=r"(r[2]), "=r"(r[3]) : "r"(saddr));
}
__device__ __forceinline__ void ldmx4t(unsigned* r, unsigned saddr) {
    asm volatile("ldmatrix.sync.aligned.m8n8.x4.trans.shared.b16 {%0,%1,%2,%3}, [%4];"
                 : "=r"(r[0]), "=r"(r[1]), "=r"(r[2]), "=r"(r[3]) : "r"(saddr));
}
__device__ __forceinline__ unsigned pack2h(float a, float b) {
    __half2 h = __floats2half2_rn(a, b);
    return *(unsigned*)&h;
}
__device__ __forceinline__ void cpa16(unsigned saddr, const void* gaddr) {
    asm volatile("cp.async.cg.shared.global [%0], [%1], 16;" :: "r"(saddr), "l"(gaddr));
}
#define CP_COMMIT() asm volatile("cp.async.commit_group;")
#define CP_WAIT1()  asm volatile("cp.async.wait_group 1;")
#define CP_WAIT0()  asm volatile("cp.async.wait_group 0;")

// PV partial-reduction helpers (pv layout: [mi][nt][u2*4 + frag]; slot = 32x32 fp32)
__device__ __forceinline__ void red_store(float* red, int slot, const float pv[2][2][8],
                                          int g, int q)
{
    #pragma unroll
    for (int mi = 0; mi < 2; mi++)
        #pragma unroll
        for (int nt = 0; nt < 2; nt++)
            #pragma unroll
            for (int u2 = 0; u2 < 2; u2++) {
                *(float2*)&red[slot * 1024 + (mi * 16 + g) * 32 + nt * 16 + u2 * 8 + 2 * q] =
                    make_float2(pv[mi][nt][u2 * 4 + 0], pv[mi][nt][u2 * 4 + 1]);
                *(float2*)&red[slot * 1024 + (mi * 16 + g + 8) * 32 + nt * 16 + u2 * 8 + 2 * q] =
                    make_float2(pv[mi][nt][u2 * 4 + 2], pv[mi][nt][u2 * 4 + 3]);
            }
}
__device__ __forceinline__ void red_load(const float* red, int slot, float pv[2][2][8],
                                         int g, int q)
{
    #pragma unroll
    for (int mi = 0; mi < 2; mi++)
        #pragma unroll
        for (int nt = 0; nt < 2; nt++)
            #pragma unroll
            for (int u2 = 0; u2 < 2; u2++) {
                float2 p0 = *(const float2*)&red[slot * 1024 + (mi * 16 + g) * 32 + nt * 16 + u2 * 8 + 2 * q];
                float2 p1 = *(const float2*)&red[slot * 1024 + (mi * 16 + g + 8) * 32 + nt * 16 + u2 * 8 + 2 * q];
                pv[mi][nt][u2 * 4 + 0] += p0.x; pv[mi][nt][u2 * 4 + 1] += p0.y;
                pv[mi][nt][u2 * 4 + 2] += p1.x; pv[mi][nt][u2 * 4 + 3] += p1.y;
            }
}

// ---------------------------------------------------------------------------
// Kernel 1: QKV projection as fp16 tensor-core GEMM (verified R15).
// ---------------------------------------------------------------------------
extern "C" __global__ void __launch_bounds__(512)
proj_kernel(const float* __restrict__ x,
            const float* __restrict__ w,
            const float* __restrict__ bias)
{
    extern __shared__ char psm[];
    float* sB = (float*)(psm + PSM_B);

    const int ct0 = blockIdx.x * 128;
    const int tid  = threadIdx.x;
    const int lane = tid & 31;
    const int wid  = tid >> 5;
    const int mw2  = wid & 3;
    const int nww  = wid >> 2;
    const int g    = lane >> 2;
    const int q    = lane & 3;

    #pragma unroll 2
    for (int i = tid; i < 192 * 32; i += 512) {
        const int j = i >> 5, dw = i & 31;
        const float2 v = *(const float2*)&w[j * 64 + dw * 2];
        *(unsigned*)(psm + PSM_W + j * 144 + dw * 4) = pack2h(v.x, v.y);
    }
    #pragma unroll 2
    for (int i = tid; i < 128 * 32; i += 512) {
        const int r = i >> 5, dw = i & 31;
        const float2 v = *(const float2*)&x[(size_t)(ct0 + r) * 64 + dw * 2];
        *(unsigned*)(psm + PSM_X + r * 144 + dw * 4) = pack2h(v.x, v.y);
    }
    if (tid < 192) sB[tid] = bias[tid];
    __syncthreads();

    const unsigned sX_sa = (unsigned)__cvta_generic_to_shared(psm + PSM_X);
    const unsigned sW_sa = (unsigned)__cvta_generic_to_shared(psm + PSM_W);
    const unsigned ax_b0 = sX_sa + (unsigned)((mw2 * 32 + (lane & 15)) * 144 + ((lane >> 4) & 1) * 16);
    const unsigned ax_b1 = ax_b0 + 16 * 144;
    const unsigned bw_row = (unsigned)(nww * 48 + ((lane >> 4) & 1) * 8 + (lane & 7));
    const unsigned bw_kc  = (unsigned)(((lane >> 3) & 1) * 16);

    float acc[2][6][4];
    #pragma unroll
    for (int mi = 0; mi < 2; mi++)
        #pragma unroll
        for (int n8 = 0; n8 < 6; n8++)
            #pragma unroll
            for (int u = 0; u < 4; u++) acc[mi][n8][u] = 0.f;

    #pragma unroll
    for (int jb = 0; jb < 4; jb++) {
        unsigned a0[4], a1[4];
        ldmx4(a0, ax_b0 + jb * 32);
        ldmx4(a1, ax_b1 + jb * 32);
        #pragma unroll
        for (int nt = 0; nt < 3; nt++) {
            unsigned bk[4];
            ldmx4(bk, sW_sa + (bw_row + nt * 16) * 144 + jb * 32 + bw_kc);
            mma_f16(acc[0][2 * nt],     a0, bk[0], bk[1]);
            mma_f16(acc[0][2 * nt + 1], a0, bk[2], bk[3]);
            mma_f16(acc[1][2 * nt],     a1, bk[0], bk[1]);
            mma_f16(acc[1][2 * nt + 1], a1, bk[2], bk[3]);
        }
    }

    #pragma unroll
    for (int mi = 0; mi < 2; mi++) {
        #pragma unroll
        for (int hf = 0; hf < 2; hf++) {
            const int rg = ct0 + mw2 * 32 + mi * 16 + hf * 8 + g;
            const int h  = rg & 15;
            const int b  = (rg >> 4) & 3;
            const int t  = rg >> 6;
            const size_t rowbase = ((size_t)(b * 16 + h) * TT + t) * HD;
            #pragma unroll
            for (int n8 = 0; n8 < 6; n8++) {
                const int j0 = nww * 48 + n8 * 8 + 2 * q;
                float v0 = acc[mi][n8][hf * 2]     + sB[j0];
                float v1 = acc[mi][n8][hf * 2 + 1] + sB[j0 + 1];
                if (j0 < 64) {
                    *(unsigned*)&g_q[rowbase + j0] = pack2h(v0 * 0.125f, v1 * 0.125f);
                } else if (j0 < 128) {
                    *(unsigned*)&g_k[rowbase + (j0 - 64)] = pack2h(v0, v1);
                } else {
                    *(unsigned*)&g_v[rowbase + (j0 - 128)] = pack2h(v0, v1);
                }
            }
        }
    }
}

// ---------------------------------------------------------------------------
__device__ __forceinline__ void stage_k(unsigned sbase, const __half* gsrc,
                                        size_t rowbase, int tid)
{
    #pragma unroll
    for (int i = tid; i < SCH * 8; i += 512) {
        const int s = i >> 3, j = i & 7;
        cpa16(sbase + s * 144 + j * 16, (const void*)(((const uint4*)gsrc) + (rowbase + s) * 8 + j));
    }
}
__device__ __forceinline__ void stage_q(unsigned sQ_sa, size_t base, int t0, int tid)
{
    const int r = tid >> 3, j = tid & 7;
    cpa16(sQ_sa + (unsigned)(r * 144 + j * 16),
          (const void*)(((const uint4*)g_q) + (base + t0 + r) * 8 + j));
}

// ---------------------------------------------------------------------------
// Kernel 2: single-pass flash attention (m=0), R15 structure + next-head
// prefetch: at the last chunk of head h, the Q/K0/V0 group for head h+1 is
// issued (buffers provably idle); the PV reduction scratch lives in V1.
// 512 threads, 64 rows/CTA.
// ---------------------------------------------------------------------------
extern "C" __global__ void __launch_bounds__(512, 1)
attn_kernel(const float* __restrict__ outw,
            const float* __restrict__ outb,
            float* __restrict__ out)    // [T][B][E]
{
    extern __shared__ char smc[];
    float* SML = (float*)(smc + OFFB_ML);           // [64][8] l partials

    const int b    = blockIdx.x;
    const int t0   = blockIdx.y * ROWS;
    const int tid  = threadIdx.x;
    const int lane = tid & 31;
    const int wid  = tid >> 5;
    const int mw   = wid >> 3;          // 0..1
    const int sw   = wid & 7;           // 0..7
    const int sv   = sw >> 1;           // 0..3 (PV k-slice)
    const int nw   = sw & 1;            // 0..1 (PV n-half)
    const int g    = lane >> 2;
    const int q    = lane & 3;

    const unsigned smem_sa = (unsigned)__cvta_generic_to_shared(smc);
    const unsigned sK0 = smem_sa + OFFB_K0;
    const unsigned sK1 = smem_sa + OFFB_K1;
    const unsigned sV0 = smem_sa + OFFB_V0;
    const unsigned sV1 = smem_sa + OFFB_V1;
    const unsigned sW_sa = smem_sa + OFFB_W;
    const unsigned sQ_sa = smem_sa + OFFB_Q;

    const unsigned aq_b0 = sQ_sa + (unsigned)((mw * 32 + (lane & 15)) * 144 + ((lane >> 4) & 1) * 16);
    const unsigned aq_b1 = aq_b0 + 16 * 144;
    const unsigned bk_row  = (unsigned)(sw * 32 + ((lane >> 4) & 1) * 8 + (lane & 7));
    const unsigned bk_kc   = (unsigned)(((lane >> 3) & 1) * 16);
    const unsigned bv_row  = (unsigned)(sv * 64 + ((lane >> 3) & 1) * 8 + (lane & 7));
    const unsigned bv_nc   = (unsigned)(nw * 64 + ((lane >> 4) & 1) * 16);
    const unsigned aw_b0 = sW_sa + (unsigned)((mw * 32 + (lane & 15)) * 528 + sv * 128 + ((lane >> 4) & 1) * 16);
    const unsigned aw_b1 = aw_b0 + 16 * 528;

    // prologue: stage head 0's Q + chunk 0
    {
        const size_t base0 = (size_t)(b * HH) * TT;
        stage_q(sQ_sa, base0, t0, tid);
        stage_k(sK0, g_k, base0, tid);
        stage_k(sV0, g_v, base0, tid);
        CP_COMMIT();
    }

    for (int h = 0; h < HH; h++) {
        const int bh = b * HH + h;
        const size_t base = (size_t)bh * TT;

        CP_WAIT0();
        __syncthreads();                 // head-h Q/K0/V0 landed (incl. prefetch path)

        unsigned aq[2][4][4];
        #pragma unroll
        for (int jb = 0; jb < 4; jb++) {
            ldmx4(aq[0][jb], aq_b0 + jb * 32);
            ldmx4(aq[1][jb], aq_b1 + jb * 32);
        }

        float pv[2][2][8];
        #pragma unroll
        for (int mi = 0; mi < 2; mi++)
            #pragma unroll
            for (int nt = 0; nt < 2; nt++)
                #pragma unroll
                for (int u = 0; u < 8; u++) pv[mi][nt][u] = 0.f;
        float lp[2][2] = {{0.f, 0.f}, {0.f, 0.f}};

        for (int c = 0; c < NCH; c++) {
            if (c + 1 < NCH) {
                stage_k((c & 1) ? sK0 : sK1, g_k, base + (size_t)(c + 1) * SCH, tid);
                stage_k((c & 1) ? sV0 : sV1, g_v, base + (size_t)(c + 1) * SCH, tid);
                CP_COMMIT();
                CP_WAIT1();
            } else if (h + 1 < HH) {
                // prefetch next head's Q + chunk 0 (K0/V0/Q idle; reads closed)
                const size_t nbase = base + TT;
                stage_q(sQ_sa, nbase, t0, tid);
                stage_k(sK0, g_k, nbase, tid);
                stage_k(sV0, g_v, nbase, tid);
                CP_COMMIT();
                CP_WAIT1();
            } else {
                CP_WAIT0();
            }
            __syncthreads();
            const unsigned sK_sa = (c & 1) ? sK1 : sK0;
            const unsigned sV_sa = (c & 1) ? sV1 : sV0;
            const int s0g = c * SCH;

            // scores per n16 tile -> p-hat = exp(s), l accumulate, pack to W stage
            #pragma unroll
            for (int nt = 0; nt < 2; nt++) {
                float sc2[2][8];
                #pragma unroll
                for (int mi = 0; mi < 2; mi++)
                    #pragma unroll
                    for (int u = 0; u < 8; u++) sc2[mi][u] = 0.f;
                #pragma unroll
                for (int jb = 0; jb < 4; jb++) {
                    unsigned bk[4];
                    ldmx4(bk, sK_sa + (bk_row + nt * 16) * 144 + jb * 32 + bk_kc);
                    #pragma unroll
                    for (int mi = 0; mi < 2; mi++) {
                        mma_f16(sc2[mi],     aq[mi][jb], bk[0], bk[1]);
                        mma_f16(sc2[mi] + 4, aq[mi][jb], bk[2], bk[3]);
                    }
                }
                #pragma unroll
                for (int mi = 0; mi < 2; mi++) {
                    #pragma unroll
                    for (int u2 = 0; u2 < 2; u2++) {
                        const float p00 = __expf(sc2[mi][u2 * 4 + 0]);
                        const float p01 = __expf(sc2[mi][u2 * 4 + 1]);
                        const float p10 = __expf(sc2[mi][u2 * 4 + 2]);
                        const float p11 = __expf(sc2[mi][u2 * 4 + 3]);
                        lp[mi][0] += p00 + p01;
                        lp[mi][1] += p10 + p11;
                        const int cloc = sw * 32 + nt * 16 + u2 * 8 + 2 * q;
                        const int r0 = mw * 32 + mi * 16 + g;
                        *(unsigned*)(smc + OFFB_W + r0 * 528 + cloc * 2)       = pack2h(p00, p01);
                        *(unsigned*)(smc + OFFB_W + (r0 + 8) * 528 + cloc * 2) = pack2h(p10, p11);
                    }
                }
            }
            __syncthreads();   // W stage ready (PV + scratch copy)

            // W chunk -> per-head p-hat plane (coalesced 16B stores)
            {
                __half* ps = g_p + ((size_t)bh * TT + t0) * TT + s0g;
                #pragma unroll
                for (int i = tid; i < 64 * 32; i += 512) {
                    const int r = i >> 5, j = i & 31;
                    *(uint4*)(ps + (size_t)r * TT + j * 8) =
                        *(const uint4*)(smc + OFFB_W + r * 528 + j * 16);
                }
            }

            // PV: warp (mw, sv, nw): k = 64 s, m = 32 rows, n = 32 d (unnormalized)
            #pragma unroll
            for (int kb = 0; kb < 4; kb++) {
                unsigned aw0[4], aw1[4];
                ldmx4(aw0, aw_b0 + kb * 32);
                ldmx4(aw1, aw_b1 + kb * 32);
                #pragma unroll
                for (int nt = 0; nt < 2; nt++) {
                    unsigned bv[4];
                    ldmx4t(bv, sV_sa + (bv_row + kb * 16) * 144 + nt * 32 + bv_nc);
                    mma_f16(pv[0][nt],     aw0, bv[0], bv[1]);
                    mma_f16(pv[0][nt] + 4, aw0, bv[2], bv[3]);
                    mma_f16(pv[1][nt],     aw1, bv[0], bv[1]);
                    mma_f16(pv[1][nt] + 4, aw1, bv[2], bv[3]);
                }
            }
            __syncthreads();
        }

        // ---- combine l across q-lanes and the 8 s-warps ----
        #pragma unroll
        for (int mi = 0; mi < 2; mi++)
            #pragma unroll
            for (int hf = 0; hf < 2; hf++) {
                float v = lp[mi][hf];
                v += __shfl_xor_sync(0xffffffffu, v, 1);
                v += __shfl_xor_sync(0xffffffffu, v, 2);
                lp[mi][hf] = v;
            }
        if (q == 0) {
            #pragma unroll
            for (int mi = 0; mi < 2; mi++)
                #pragma unroll
                for (int hf = 0; hf < 2; hf++) {
                    const int ri = mw * 32 + mi * 16 + hf * 8 + g;
                    SML[ri * 8 + sw] = lp[mi][hf];
                }
        }
        __syncthreads();
        float inv[2][2];
        #pragma unroll
        for (int mi = 0; mi < 2; mi++)
            #pragma unroll
            for (int hf = 0; hf < 2; hf++) {
                const int ri = mw * 32 + mi * 16 + hf * 8 + g;
                float lf = 0.f;
                #pragma unroll
                for (int i = 0; i < 8; i++) lf += SML[ri * 8 + i];
                inv[mi][hf] = 1.f / lf;
            }
        if (sw == 0 && q == 0) {
            #pragma unroll
            for (int mi = 0; mi < 2; mi++)
                #pragma unroll
                for (int hf = 0; hf < 2; hf++) {
                    const int ri = mw * 32 + mi * 16 + hf * 8 + g;
                    g_il[(size_t)bh * TT + t0 + ri] = inv[mi][hf] * (1.f / HH);
                }
        }

        // ---- reduce PV partials across 4 sv-slices per (mw, nw) group ----
        // scratch in V1 region (idle; K0/V0/Q hold the in-flight next-head prefetch)
        float* red = (float*)(smc + OFFB_V1);   // 8 slots of 32x32 fp32 = 32KB
        const int group = mw * 2 + nw;
        if (sv >= 2) red_store(red, group * 2 + (sv - 2), pv, g, q);
        __syncthreads();
        if (sv < 2) red_load(red, group * 2 + sv, pv, g, q);
        __syncthreads();
        if (sv == 1) red_store(red, group * 2 + 1, pv, g, q);
        __syncthreads();
        float* so = (float*)(smc + OFFB_W);     // [64][OST] fp32
        if (sv == 0) {
            red_load(red, group * 2 + 1, pv, g, q);
            #pragma unroll
            for (int mi = 0; mi < 2; mi++)
                #pragma unroll
                for (int nt = 0; nt < 2; nt++)
                    #pragma unroll
                    for (int u2 = 0; u2 < 2; u2++) {
                        const int col = nw * 32 + nt * 16 + u2 * 8 + 2 * q;
                        const int r0  = mw * 32 + mi * 16 + g;
                        *(float2*)&so[r0 * OST + col] =
                            make_float2(pv[mi][nt][u2 * 4 + 0] * inv[mi][0],
                                        pv[mi][nt][u2 * 4 + 1] * inv[mi][0]);
                        *(float2*)&so[(r0 + 8) * OST + col] =
                            make_float2(pv[mi][nt][u2 * 4 + 2] * inv[mi][1],
                                        pv[mi][nt][u2 * 4 + 3] * inv[mi][1]);
                    }
        }
        __syncthreads();

        // ---- out projection ----
        {
            const int e  = tid & 63;
            const int rg = tid >> 6;            // 0..7 -> 8 rows each
            float oc[8];
            const float ob = outb[e];
            #pragma unroll
            for (int k = 0; k < 8; k++) oc[k] = ob;
            #pragma unroll 8
            for (int d = 0; d < 64; d++) {
                const float wv = outw[e * HD + d];
                #pragma unroll
                for (int k = 0; k < 8; k++)
                    oc[k] += so[(rg * 8 + k) * OST + d] * wv;
            }
            #pragma unroll
            for (int k = 0; k < 8; k++)
                out[((size_t)(t0 + rg * 8 + k) * BB + b) * EE + h * HD + e] = oc[k];
        }
        __syncthreads();
    }
}

// ---------------------------------------------------------------------------
// Kernel 3: avg finalize (verified R14/R15).
// ---------------------------------------------------------------------------
extern "C" __global__ void __launch_bounds__(256)
avg_kernel(float* __restrict__ avg)     // [B][T][T]
{
    const int bt = blockIdx.x;
    const int b  = bt >> 11;
    const int t  = bt & (TT - 1);
    const int tid = threadIdx.x;

    __shared__ float il[HH];
    if (tid < HH) il[tid] = g_il[(size_t)(b * HH + tid) * TT + t];
    __syncthreads();

    const int s0 = tid * 8;
    float acc[8] = {};
    #pragma unroll
    for (int h = 0; h < HH; h++) {
        const uint4 pk = *(const uint4*)(g_p + ((size_t)(b * HH + h) * TT + t) * TT + s0);
        const float s = il[h];
        const __half2* ph = (const __half2*)&pk;
        #pragma unroll
        for (int j = 0; j < 4; j++) {
            float2 f = __half22float2(ph[j]);
            acc[2 * j]     += f.x * s;
            acc[2 * j + 1] += f.y * s;
        }
    }
    float* dst = avg + ((size_t)b * TT + t) * TT + s0;
    *(float4*)dst       = make_float4(acc[0], acc[1], acc[2], acc[3]);
    *(float4*)(dst + 4) = make_float4(acc[4], acc[5], acc[6], acc[7]);
}

// ---------------------------------------------------------------------------
extern "C" void kernel_launch(void* const* d_in, const int* in_sizes, int n_in,
                              void* d_out, int out_size)
{
    const float* x    = (const float*)d_in[0];
    const float* w    = (const float*)d_in[1];
    const float* bias = (const float*)d_in[2];
    const float* outw = (const float*)d_in[3];
    const float* outb = (const float*)d_in[4];

    float* out = (float*)d_out;
    float* avg = out + (size_t)TT * BB * EE;

    static bool attrs_set = false;
    if (!attrs_set) {
        cudaFuncSetAttribute(proj_kernel, cudaFuncAttributeMaxDynamicSharedMemorySize, PSM_BYTES);
        cudaFuncSetAttribute(attn_kernel, cudaFuncAttributeMaxDynamicSharedMemorySize, SMEM_BYTES);
        attrs_set = true;
    }

    proj_kernel<<<(TT * BB * HH) / 128, 512, PSM_BYTES>>>(x, w, bias);
    attn_kernel<<<dim3(BB, TT / ROWS), 512, SMEM_BYTES>>>(outw, outb, out);
    avg_kernel<<<BB * TT, 256>>>(avg);
}